// round 14
// baseline (speedup 1.0000x reference)
#include <cuda_runtime.h>
#include <cuda_bf16.h>
#include <cstdint>
#include <math_constants.h>

#define BATCH 32
#define SLEN  2048
#define DDIM  128
#define HDIM  256
#define KCODE 512

// ---------------- scratch (static device globals; no allocation) ----------------
__device__ float g_h1[(size_t)BATCH * HDIM * SLEN];   // 64 MB  enc, channel-first
__device__ float g_h2[(size_t)BATCH * HDIM * SLEN];   // 64 MB  enc, channel-first
__device__ float g_z [(size_t)BATCH * DDIM * SLEN];   // 32 MB  channel-first
__device__ float g_zq[(size_t)BATCH * SLEN * DDIM];   // 32 MB  channel-last (feeds MMA dec)
__device__ float g_d1[(size_t)BATCH * SLEN * HDIM];   // 64 MB  dec1 out channel-last
__device__ float g_d2[(size_t)BATCH * SLEN * HDIM];   // 64 MB  dec2 out channel-last
__device__ __nv_bfloat16 g_wh[HDIM * 3 * HDIM];       // K-major weight hi (bf16)
__device__ __nv_bfloat16 g_wl[HDIM * 3 * HDIM];       // K-major weight lo (bf16)
__device__ float g_c2[KCODE];
__device__ double g_acc[2];                            // [0]=sum min dist, [1]=recon SSE

// ---------------- helpers ----------------
typedef unsigned long long u64;

__device__ __forceinline__ u64 pack2(float lo, float hi) {
    u64 r;
    asm("mov.b64 %0, {%1, %2};" : "=l"(r) : "f"(lo), "f"(hi));
    return r;
}
__device__ __forceinline__ u64 bcast2(float v) {
    u64 r;
    asm("mov.b64 %0, {%1, %1};" : "=l"(r) : "f"(v));
    return r;
}
__device__ __forceinline__ void unpack2(u64 p, float& lo, float& hi) {
    asm("mov.b64 {%0, %1}, %2;" : "=f"(lo), "=f"(hi) : "l"(p));
}
// packed dual fp32 FMA: per-lane identical to scalar FFMA (rn, fused)
__device__ __forceinline__ void fma2(u64& d, u64 a, u64 b) {
    asm("fma.rn.f32x2 %0, %1, %2, %0;" : "+l"(d) : "l"(a), "l"(b));
}

__device__ __forceinline__ uint32_t pack_hi(float v0, float v1, float& r0, float& r1) {
    __nv_bfloat16 h0 = __float2bfloat16_rn(v0);
    __nv_bfloat16 h1 = __float2bfloat16_rn(v1);
    r0 = v0 - __bfloat162float(h0);
    r1 = v1 - __bfloat162float(h1);
    return ((uint32_t)__bfloat16_as_ushort(h1) << 16) | (uint32_t)__bfloat16_as_ushort(h0);
}
__device__ __forceinline__ uint32_t pack_lo(float r0, float r1) {
    __nv_bfloat16 l0 = __float2bfloat16_rn(r0);
    __nv_bfloat16 l1 = __float2bfloat16_rn(r1);
    return ((uint32_t)__bfloat16_as_ushort(l1) << 16) | (uint32_t)__bfloat16_as_ushort(l0);
}

__device__ __forceinline__ void mma16816(float* d, const uint32_t* a, const uint32_t* b) {
    asm volatile(
        "mma.sync.aligned.m16n8k16.row.col.f32.bf16.bf16.f32 "
        "{%0,%1,%2,%3}, {%4,%5,%6,%7}, {%8,%9}, {%0,%1,%2,%3};"
        : "+f"(d[0]), "+f"(d[1]), "+f"(d[2]), "+f"(d[3])
        : "r"(a[0]), "r"(a[1]), "r"(a[2]), "r"(a[3]), "r"(b[0]), "r"(b[1]));
}

// ---------------- init ----------------
__global__ void init_k() {
    if (threadIdx.x < 2) g_acc[threadIdx.x] = 0.0;
}

// ---------------- codebook norms ----------------
__global__ void c2_k(const float* __restrict__ cb) {
    int k = blockIdx.x * blockDim.x + threadIdx.x;
    if (k < KCODE) {
        const float* r = cb + (size_t)k * DDIM;
        float s = 0.f;
        #pragma unroll 8
        for (int d = 0; d < DDIM; d++) s += r[d] * r[d];
        g_c2[k] = s;
    }
}

// ---------------- encoder conv1: 1 -> H, k=3, SAME, lrelu (round-1 proven) ---
__global__ __launch_bounds__(256) void enc1_k(const float* __restrict__ x,
                                              const float* __restrict__ w,
                                              const float* __restrict__ bias) {
    size_t idx = (size_t)blockIdx.x * blockDim.x + threadIdx.x;   // over B*H*S
    int s = idx & (SLEN - 1);
    int c = (idx >> 11) & (HDIM - 1);
    int b = idx >> 19;
    const float* xb = x + (size_t)b * SLEN;
    float v = bias[c];
    float w0 = w[c*3+0], w1 = w[c*3+1], w2 = w[c*3+2];
    if (s > 0)        v += w0 * xb[s-1];
    v += w1 * xb[s];
    if (s < SLEN - 1) v += w2 * xb[s+1];
    g_h1[idx] = (v >= 0.f) ? v : 0.2f * v;
}

// ------------ SIMT fp32 conv, f32x2-packed, vectorized LDS (bit-identical) ------------
template<int CI, int CO, bool RELU>
__global__ __launch_bounds__(256) void conv_k(const float* __restrict__ in,
                                              const float* __restrict__ w,
                                              const float* __restrict__ bias,
                                              float* __restrict__ out) {
    const int s_tile  = blockIdx.x * 64;
    const int co_base = blockIdx.y * 128;
    const int b       = blockIdx.z;
    const int tid = threadIdx.x;
    const int tx  = tid & 15;    // s group   (4 outputs)
    const int ty  = tid >> 4;    // co group  (8 outputs = 4 packed pairs)

    __shared__ __align__(16) float ws[48 * 132];   // [ci*3+t][co], stride 132 (16B multiple)
    __shared__ __align__(16) float ins[16][72];    // [ci][sp]

    u64 accp[4][4];
    #pragma unroll
    for (int vp = 0; vp < 4; vp++)
        #pragma unroll
        for (int u = 0; u < 4; u++) accp[vp][u] = 0ULL;

    const float* in_b = in + (size_t)b * CI * SLEN;

    for (int ci0 = 0; ci0 < CI; ci0 += 16) {
        __syncthreads();
        for (int i = tid; i < 16 * 66; i += 256) {
            int ci = i / 66, sp = i - ci * 66;
            int s = s_tile - 1 + sp;
            float v = 0.f;
            if (s >= 0 && s < SLEN) v = in_b[(size_t)(ci0 + ci) * SLEN + s];
            ins[ci][sp] = v;
        }
        for (int i = tid; i < 128 * 48; i += 256) {
            int co = i / 48, j = i - co * 48;            // j = ci_local*3 + t
            ws[j * 132 + co] = w[(size_t)(co_base + co) * (CI * 3) + (size_t)ci0 * 3 + j];
        }
        __syncthreads();

        #pragma unroll
        for (int ci = 0; ci < 16; ci++) {
            // xv[0..7] via two LDS.128 (need 0..5)
            float4 xa = *reinterpret_cast<const float4*>(&ins[ci][tx * 4]);
            float4 xc = *reinterpret_cast<const float4*>(&ins[ci][tx * 4 + 4]);
            u64 xp[6];
            xp[0] = bcast2(xa.x); xp[1] = bcast2(xa.y); xp[2] = bcast2(xa.z);
            xp[3] = bcast2(xa.w); xp[4] = bcast2(xc.x); xp[5] = bcast2(xc.y);
            #pragma unroll
            for (int t = 0; t < 3; t++) {
                const longlong2* wrow =
                    reinterpret_cast<const longlong2*>(&ws[(ci * 3 + t) * 132 + ty * 8]);
                longlong2 wA = wrow[0];   // packed co pairs (0,1) and (2,3)
                longlong2 wB = wrow[1];   // packed co pairs (4,5) and (6,7)
                #pragma unroll
                for (int u = 0; u < 4; u++) {
                    fma2(accp[0][u], (u64)wA.x, xp[u + t]);
                    fma2(accp[1][u], (u64)wA.y, xp[u + t]);
                    fma2(accp[2][u], (u64)wB.x, xp[u + t]);
                    fma2(accp[3][u], (u64)wB.y, xp[u + t]);
                }
            }
        }
    }

    #pragma unroll
    for (int vp = 0; vp < 4; vp++) {
        int co0 = co_base + ty * 8 + 2 * vp;
        float bb0 = bias[co0];
        float bb1 = bias[co0 + 1];
        #pragma unroll
        for (int u = 0; u < 4; u++) {
            float a0, a1;
            unpack2(accp[vp][u], a0, a1);
            int s = s_tile + tx * 4 + u;
            float r0 = a0 + bb0;
            float r1 = a1 + bb1;
            if (RELU) {
                r0 = (r0 >= 0.f) ? r0 : 0.2f * r0;
                r1 = (r1 >= 0.f) ? r1 : 0.2f * r1;
            }
            out[((size_t)b * CO + co0) * SLEN + s]     = r0;
            out[((size_t)b * CO + co0 + 1) * SLEN + s] = r1;
        }
    }
}

// ------- VQ: bit-exact argmin (round-13 proven), f32x2-packed dots -------
__global__ __launch_bounds__(256) void vq_k(const float* __restrict__ cb,
                                            float* __restrict__ out_idx) {
    __shared__ __align__(16) float4 cbs[64 * 32];   // 64 codes x 128 floats = 32 KB
    __shared__ float  c2s[64];

    int gp = blockIdx.x * 256 + threadIdx.x;     // global position in [0, B*S)
    int b = gp >> 11;
    int s = gp & (SLEN - 1);

    const float* zb = g_z + (size_t)b * DDIM * SLEN + s;
    u64 zp[64];
    float z2 = 0.f;
    #pragma unroll
    for (int q = 0; q < 64; q++) {
        float a0 = zb[(size_t)(2 * q) * SLEN];
        float a1 = zb[(size_t)(2 * q + 1) * SLEN];
        zp[q] = pack2(a0, a1);
        z2 += a0 * a0;
        z2 += a1 * a1;
    }

    float best = CUDART_INF_F;
    int bi = 0;
    const float4* cb4 = reinterpret_cast<const float4*>(cb);

    for (int kc = 0; kc < KCODE; kc += 64) {
        __syncthreads();
        #pragma unroll
        for (int i = threadIdx.x; i < 64 * 32; i += 256)
            cbs[i] = cb4[kc * 32 + i];
        if (threadIdx.x < 64) c2s[threadIdx.x] = g_c2[kc + threadIdx.x];
        __syncthreads();

        for (int kk = 0; kk < 64; kk++) {
            const u64* cp = reinterpret_cast<const u64*>(&cbs[kk * 32]);
            u64 d01 = 0ULL, d23 = 0ULL;     // lanes: (d0,d1), (d2,d3)
            #pragma unroll
            for (int q = 0; q < 32; q++) {
                fma2(d01, cp[2 * q],     zp[2 * q]);
                fma2(d23, cp[2 * q + 1], zp[2 * q + 1]);
            }
            float d0, d1, d2, d3;
            unpack2(d01, d0, d1);
            unpack2(d23, d2, d3);
            float dist = z2 + c2s[kk] - 2.f * ((d0 + d1) + (d2 + d3));
            if (dist < best) { best = dist; bi = kc + kk; }
        }
    }

    out_idx[gp] = (float)bi;

    const float* cc = cb + (size_t)bi * DDIM;
    float4* zq = reinterpret_cast<float4*>(g_zq + (size_t)gp * DDIM);
    float qs = 0.f;
    #pragma unroll
    for (int q = 0; q < 64; q++) {
        float a0, a1;
        unpack2(zp[q], a0, a1);
        float df0 = a0 - cc[2 * q];
        qs += df0 * df0;
        float df1 = a1 - cc[2 * q + 1];
        qs += df1 * df1;
    }
    #pragma unroll
    for (int q = 0; q < 32; q++) zq[q] = __ldg(reinterpret_cast<const float4*>(cc) + q);

    __shared__ float red[256];
    red[threadIdx.x] = qs;
    __syncthreads();
    for (int off = 128; off > 0; off >>= 1) {
        if (threadIdx.x < off) red[threadIdx.x] += red[threadIdx.x + off];
        __syncthreads();
    }
    if (threadIdx.x == 0) atomicAdd(&g_acc[0], (double)red[0]);
}

// weight prep: [CO][ci*3+t] fp32 -> K-major [CO][t*CI+ci] bf16 hi/lo
template<int CO, int CI>
__global__ __launch_bounds__(256) void wprep_k(const float* __restrict__ w,
                                               __nv_bfloat16* __restrict__ wh,
                                               __nv_bfloat16* __restrict__ wl) {
    int idx = blockIdx.x * 256 + threadIdx.x;        // over CO*3*CI
    int co = idx / (3 * CI);
    int r  = idx - co * (3 * CI);                    // = t*CI + ci
    int t  = r / CI;
    int ci = r - t * CI;
    float v = w[(size_t)co * 3 * CI + (size_t)ci * 3 + t];
    __nv_bfloat16 h = __float2bfloat16_rn(v);
    wh[idx] = h;
    wl[idx] = __float2bfloat16_rn(v - __bfloat162float(h));
}

// ============ bf16 hi/lo 3-term HMMA conv (round-11 proven): CI -> CO ============
template<int CI, int CO, bool RELU>
__global__ __launch_bounds__(256, 2) void conv_mma_k(const float* __restrict__ in,
                                                     const __nv_bfloat16* __restrict__ wh,
                                                     const __nv_bfloat16* __restrict__ wl,
                                                     const float* __restrict__ bias,
                                                     float* __restrict__ out) {
    constexpr int KTOT = 3 * CI;
    constexpr int NCH  = KTOT / 32;
    constexpr int RSTR = 80;                 // bytes per smem row (32 bf16 + 16 pad)

    __shared__ __align__(16) char smem_[4 * 128 * RSTR];   // 40 KB
    char* Ah = smem_;
    char* Al = smem_ + 128 * RSTR;
    char* Bh = smem_ + 2 * 128 * RSTR;
    char* Bl = smem_ + 3 * 128 * RSTR;

    const int tid  = threadIdx.x;
    const int lane = tid & 31;
    const int wid  = tid >> 5;
    const int wm   = wid & 1;                // 2 warps over co
    const int wn   = wid >> 1;               // 4 warps over p
    const int g    = lane >> 2;              // group id 0..7
    const int t4   = lane & 3;               // thread-in-group 0..3

    const int bs_base = blockIdx.x * 128;
    const int co_base = blockIdx.y * 128;
    const int s_in_b0 = bs_base & (SLEN - 1);

    float acc[4][4][4];
    #pragma unroll
    for (int i = 0; i < 4; i++)
        #pragma unroll
        for (int j = 0; j < 4; j++)
            #pragma unroll
            for (int e = 0; e < 4; e++) acc[i][j][e] = 0.f;

    for (int kc = 0; kc < NCH; kc++) {
        const int t   = (kc * 32) / CI;       // tap (chunk never crosses taps; CI%32==0)
        const int ci0 = (kc * 32) % CI;
        __syncthreads();

        #pragma unroll
        for (int j = 0; j < 2; j++) {
            int idx = tid + 256 * j;          // 512 uint4
            int row = idx >> 2, q = idx & 3;
            size_t src = (size_t)(co_base + row) * KTOT + kc * 32;
            uint4 vh = reinterpret_cast<const uint4*>(wh + src)[q];
            uint4 vl = reinterpret_cast<const uint4*>(wl + src)[q];
            *reinterpret_cast<uint4*>(Ah + row * RSTR + q * 16) = vh;
            *reinterpret_cast<uint4*>(Al + row * RSTR + q * 16) = vl;
        }
        #pragma unroll
        for (int j = 0; j < 4; j++) {
            int idx = tid + 256 * j;          // 1024 float4
            int row = idx >> 3, q = idx & 7;
            int sb = s_in_b0 + row + t - 1;
            float4 v = make_float4(0.f, 0.f, 0.f, 0.f);
            if (sb >= 0 && sb < SLEN)
                v = *reinterpret_cast<const float4*>(
                        in + (size_t)(bs_base + row + t - 1) * CI + ci0 + 4 * q);
            float r0, r1, r2, r3;
            uint32_t hp0 = pack_hi(v.x, v.y, r0, r1);
            uint32_t hp1 = pack_hi(v.z, v.w, r2, r3);
            *reinterpret_cast<uint2*>(Bh + row * RSTR + q * 8) = make_uint2(hp0, hp1);
            *reinterpret_cast<uint2*>(Bl + row * RSTR + q * 8) =
                make_uint2(pack_lo(r0, r1), pack_lo(r2, r3));
        }
        __syncthreads();

        #pragma unroll
        for (int ks = 0; ks < 2; ks++) {
            const int kb = ks * 32 + t4 * 4;  // byte offset of this thread's k pair
            uint32_t bh[4][2], bl[4][2];
            #pragma unroll
            for (int nf = 0; nf < 4; nf++) {
                int nrow = wn * 32 + nf * 8 + g;
                bh[nf][0] = *reinterpret_cast<uint32_t*>(Bh + nrow * RSTR + kb);
                bh[nf][1] = *reinterpret_cast<uint32_t*>(Bh + nrow * RSTR + kb + 16);
                bl[nf][0] = *reinterpret_cast<uint32_t*>(Bl + nrow * RSTR + kb);
                bl[nf][1] = *reinterpret_cast<uint32_t*>(Bl + nrow * RSTR + kb + 16);
            }
            #pragma unroll
            for (int mf = 0; mf < 4; mf++) {
                int mrow = wm * 64 + mf * 16 + g;
                uint32_t ah[4], al[4];
                ah[0] = *reinterpret_cast<uint32_t*>(Ah + mrow * RSTR + kb);
                ah[1] = *reinterpret_cast<uint32_t*>(Ah + (mrow + 8) * RSTR + kb);
                ah[2] = *reinterpret_cast<uint32_t*>(Ah + mrow * RSTR + kb + 16);
                ah[3] = *reinterpret_cast<uint32_t*>(Ah + (mrow + 8) * RSTR + kb + 16);
                al[0] = *reinterpret_cast<uint32_t*>(Al + mrow * RSTR + kb);
                al[1] = *reinterpret_cast<uint32_t*>(Al + (mrow + 8) * RSTR + kb);
                al[2] = *reinterpret_cast<uint32_t*>(Al + mrow * RSTR + kb + 16);
                al[3] = *reinterpret_cast<uint32_t*>(Al + (mrow + 8) * RSTR + kb + 16);
                #pragma unroll
                for (int nf = 0; nf < 4; nf++) {
                    mma16816(acc[mf][nf], ah, bh[nf]);
                    mma16816(acc[mf][nf], ah, bl[nf]);
                    mma16816(acc[mf][nf], al, bh[nf]);
                }
            }
        }
    }

    #pragma unroll
    for (int mf = 0; mf < 4; mf++) {
        int co0 = co_base + wm * 64 + mf * 16 + g;
        float bb0 = bias[co0];
        float bb1 = bias[co0 + 8];
        #pragma unroll
        for (int nf = 0; nf < 4; nf++) {
            int p = bs_base + wn * 32 + nf * 8 + t4 * 2;
            #pragma unroll
            for (int e = 0; e < 2; e++) {
                float v0 = acc[mf][nf][e] + bb0;       // row g,   col t4*2+e
                float v1 = acc[mf][nf][2 + e] + bb1;   // row g+8, col t4*2+e
                if (RELU) {
                    v0 = (v0 >= 0.f) ? v0 : 0.2f * v0;
                    v1 = (v1 >= 0.f) ? v1 : 0.2f * v1;
                }
                out[(size_t)(p + e) * CO + co0]     = v0;
                out[(size_t)(p + e) * CO + co0 + 8] = v1;
            }
        }
    }
}

// ---------------- decoder conv3: H -> 1 (channel-last input) + recon loss ----
__global__ __launch_bounds__(256) void dec3_k(const float* __restrict__ hin,
                                              const float* __restrict__ w,
                                              const float* __restrict__ bias,
                                              const float* __restrict__ x,
                                              float* __restrict__ xrec) {
    __shared__ float ws[HDIM * 3];
    for (int i = threadIdx.x; i < HDIM * 3; i += 256) ws[i] = w[i];
    __syncthreads();

    int wid = threadIdx.x >> 5, lane = threadIdx.x & 31;
    int p = blockIdx.x * 8 + wid;     // global position
    int s = p & (SLEN - 1);

    float acc = 0.f;
    #pragma unroll
    for (int t = 0; t < 3; t++) {
        int sb = s + t - 1;
        if (sb < 0 || sb >= SLEN) continue;
        const float4* r = reinterpret_cast<const float4*>(hin + (size_t)(p + t - 1) * HDIM);
        #pragma unroll
        for (int q = 0; q < 2; q++) {
            float4 v = r[lane * 2 + q];
            int c0 = lane * 8 + q * 4;
            acc += v.x * ws[(c0+0)*3+t] + v.y * ws[(c0+1)*3+t]
                 + v.z * ws[(c0+2)*3+t] + v.w * ws[(c0+3)*3+t];
        }
    }
    #pragma unroll
    for (int off = 16; off > 0; off >>= 1)
        acc += __shfl_xor_sync(0xFFFFFFFFu, acc, off);

    __shared__ float wsum[8];
    if (lane == 0) {
        float a = acc + bias[0];
        xrec[p] = a;
        float diff = x[p] - a;
        wsum[wid] = diff * diff;
    }
    __syncthreads();
    if (threadIdx.x == 0) {
        float s8 = 0.f;
        #pragma unroll
        for (int i = 0; i < 8; i++) s8 += wsum[i];
        atomicAdd(&g_acc[1], (double)s8);
    }
}

// ---------------- finalize losses ----------------
__global__ void fin_k(float* __restrict__ out) {
    double qsum = g_acc[0];
    double rsum = g_acc[1];
    float qm    = (float)(qsum / ((double)BATCH * SLEN * DDIM));
    float recon = (float)(rsum / ((double)BATCH * SLEN));
    float vq    = qm * 0.05f;
    float com   = qm * 0.15f;
    size_t base = (size_t)2 * BATCH * SLEN;
    out[base + 0] = recon + vq + com;
    out[base + 1] = recon;
    out[base + 2] = vq;
    out[base + 3] = com;
}

// ---------------- launch ----------------
extern "C" void kernel_launch(void* const* d_in, const int* in_sizes, int n_in,
                              void* d_out, int out_size) {
    const float* x   = (const float*)d_in[0];
    const float* cb  = (const float*)d_in[1];
    const float* ew1 = (const float*)d_in[2];
    const float* eb1 = (const float*)d_in[3];
    const float* ew2 = (const float*)d_in[4];
    const float* eb2 = (const float*)d_in[5];
    const float* ew3 = (const float*)d_in[6];
    const float* eb3 = (const float*)d_in[7];
    const float* dw1 = (const float*)d_in[8];
    const float* db1 = (const float*)d_in[9];
    const float* dw2 = (const float*)d_in[10];
    const float* db2 = (const float*)d_in[11];
    const float* dw3 = (const float*)d_in[12];
    const float* db3 = (const float*)d_in[13];
    float* out = (float*)d_out;

    float *h1, *h2, *z, *zq, *d1, *d2;
    __nv_bfloat16 *wh, *wl;
    cudaGetSymbolAddress((void**)&h1, g_h1);
    cudaGetSymbolAddress((void**)&h2, g_h2);
    cudaGetSymbolAddress((void**)&z,  g_z);
    cudaGetSymbolAddress((void**)&zq, g_zq);
    cudaGetSymbolAddress((void**)&d1, g_d1);
    cudaGetSymbolAddress((void**)&d2, g_d2);
    cudaGetSymbolAddress((void**)&wh, g_wh);
    cudaGetSymbolAddress((void**)&wl, g_wl);

    init_k<<<1, 32>>>();
    c2_k<<<2, 256>>>(cb);

    // ---------- encoder: fp32 SIMT path, f32x2-packed (bit-identical values) ----------
    enc1_k<<<(BATCH * HDIM * SLEN) / 256, 256>>>(x, ew1, eb1);

    dim3 g2(SLEN / 64, HDIM / 128, BATCH);
    conv_k<HDIM, HDIM, true><<<g2, 256>>>(h1, ew2, eb2, h2);

    dim3 g3(SLEN / 64, DDIM / 128, BATCH);
    conv_k<HDIM, DDIM, false><<<g3, 256>>>(h2, ew3, eb3, z);

    // ---------- VQ: bit-exact argmin, f32x2-packed dots ----------
    vq_k<<<(BATCH * SLEN) / 256, 256>>>(cb, out + (size_t)BATCH * SLEN);

    // ---------- decoder: bf16 hi/lo 3-term HMMA (round-11 proven) ----------
    const int STILES = (BATCH * SLEN) / 128;   // 512

    wprep_k<HDIM, DDIM><<<(HDIM * 3 * DDIM) / 256, 256>>>(dw1, wh, wl);
    conv_mma_k<DDIM, HDIM, true><<<dim3(STILES, HDIM / 128), 256>>>(
        zq, wh, wl, db1, d1);

    wprep_k<HDIM, HDIM><<<(HDIM * 3 * HDIM) / 256, 256>>>(dw2, wh, wl);
    conv_mma_k<HDIM, HDIM, true><<<dim3(STILES, HDIM / 128), 256>>>(
        d1, wh, wl, db2, d2);

    dec3_k<<<(BATCH * SLEN) / 8, 256>>>(d2, dw3, db3, x, out);

    fin_k<<<1, 1>>>(out);
}

// round 15
// speedup vs baseline: 1.6752x; 1.6752x over previous
#include <cuda_runtime.h>
#include <cuda_bf16.h>
#include <cstdint>
#include <math_constants.h>

#define BATCH 32
#define SLEN  2048
#define DDIM  128
#define HDIM  256
#define KCODE 512

// ---------------- scratch (static device globals; no allocation) ----------------
__device__ float g_h1[(size_t)BATCH * HDIM * SLEN];   // 64 MB  enc, channel-first
__device__ float g_h2[(size_t)BATCH * HDIM * SLEN];   // 64 MB  enc, channel-first
__device__ float g_z [(size_t)BATCH * DDIM * SLEN];   // 32 MB  channel-first
__device__ float g_zq[(size_t)BATCH * SLEN * DDIM];   // 32 MB  channel-last (feeds MMA dec)
__device__ float g_d1[(size_t)BATCH * SLEN * HDIM];   // 64 MB  dec1 out channel-last
__device__ float g_d2[(size_t)BATCH * SLEN * HDIM];   // 64 MB  dec2 out channel-last
__device__ __nv_bfloat16 g_wh[HDIM * 3 * HDIM];       // K-major weight hi (bf16)
__device__ __nv_bfloat16 g_wl[HDIM * 3 * HDIM];       // K-major weight lo (bf16)
__device__ float g_c2[KCODE];
__device__ double g_acc[2];                            // [0]=sum min dist, [1]=recon SSE

// ---------------- helpers ----------------
typedef unsigned long long u64;

__device__ __forceinline__ u64 pack2(float lo, float hi) {
    u64 r;
    asm("mov.b64 %0, {%1, %2};" : "=l"(r) : "f"(lo), "f"(hi));
    return r;
}
__device__ __forceinline__ u64 bcast2(float v) {
    u64 r;
    asm("mov.b64 %0, {%1, %1};" : "=l"(r) : "f"(v));
    return r;
}
__device__ __forceinline__ void unpack2(u64 p, float& lo, float& hi) {
    asm("mov.b64 {%0, %1}, %2;" : "=f"(lo), "=f"(hi) : "l"(p));
}
// packed dual fp32 FMA: per-lane identical to scalar FFMA (rn, fused)
__device__ __forceinline__ void fma2(u64& d, u64 a, u64 b) {
    asm("fma.rn.f32x2 %0, %1, %2, %0;" : "+l"(d) : "l"(a), "l"(b));
}

__device__ __forceinline__ uint32_t pack_hi(float v0, float v1, float& r0, float& r1) {
    __nv_bfloat16 h0 = __float2bfloat16_rn(v0);
    __nv_bfloat16 h1 = __float2bfloat16_rn(v1);
    r0 = v0 - __bfloat162float(h0);
    r1 = v1 - __bfloat162float(h1);
    return ((uint32_t)__bfloat16_as_ushort(h1) << 16) | (uint32_t)__bfloat16_as_ushort(h0);
}
__device__ __forceinline__ uint32_t pack_lo(float r0, float r1) {
    __nv_bfloat16 l0 = __float2bfloat16_rn(r0);
    __nv_bfloat16 l1 = __float2bfloat16_rn(r1);
    return ((uint32_t)__bfloat16_as_ushort(l1) << 16) | (uint32_t)__bfloat16_as_ushort(l0);
}

__device__ __forceinline__ void mma16816(float* d, const uint32_t* a, const uint32_t* b) {
    asm volatile(
        "mma.sync.aligned.m16n8k16.row.col.f32.bf16.bf16.f32 "
        "{%0,%1,%2,%3}, {%4,%5,%6,%7}, {%8,%9}, {%0,%1,%2,%3};"
        : "+f"(d[0]), "+f"(d[1]), "+f"(d[2]), "+f"(d[3])
        : "r"(a[0]), "r"(a[1]), "r"(a[2]), "r"(a[3]), "r"(b[0]), "r"(b[1]));
}

// ---------------- init ----------------
__global__ void init_k() {
    if (threadIdx.x < 2) g_acc[threadIdx.x] = 0.0;
}

// ---------------- codebook norms ----------------
__global__ void c2_k(const float* __restrict__ cb) {
    int k = blockIdx.x * blockDim.x + threadIdx.x;
    if (k < KCODE) {
        const float* r = cb + (size_t)k * DDIM;
        float s = 0.f;
        #pragma unroll 8
        for (int d = 0; d < DDIM; d++) s += r[d] * r[d];
        g_c2[k] = s;
    }
}

// ---------------- encoder conv1: 1 -> H, k=3, SAME, lrelu (round-1 proven) ---
__global__ __launch_bounds__(256) void enc1_k(const float* __restrict__ x,
                                              const float* __restrict__ w,
                                              const float* __restrict__ bias) {
    size_t idx = (size_t)blockIdx.x * blockDim.x + threadIdx.x;   // over B*H*S
    int s = idx & (SLEN - 1);
    int c = (idx >> 11) & (HDIM - 1);
    int b = idx >> 19;
    const float* xb = x + (size_t)b * SLEN;
    float v = bias[c];
    float w0 = w[c*3+0], w1 = w[c*3+1], w2 = w[c*3+2];
    if (s > 0)        v += w0 * xb[s-1];
    v += w1 * xb[s];
    if (s < SLEN - 1) v += w2 * xb[s+1];
    g_h1[idx] = (v >= 0.f) ? v : 0.2f * v;
}

// ------------ SIMT fp32 conv, f32x2-packed (R13 idioms), s-tile 128 ------------
// Each thread computes 8 co x 8 s (two s-groups 64 apart, same weight regs).
template<int CI, int CO, bool RELU>
__global__ __launch_bounds__(256) void conv_k(const float* __restrict__ in,
                                              const float* __restrict__ w,
                                              const float* __restrict__ bias,
                                              float* __restrict__ out) {
    const int s_tile  = blockIdx.x * 128;
    const int co_base = blockIdx.y * 128;
    const int b       = blockIdx.z;
    const int tid = threadIdx.x;
    const int tx  = tid & 15;    // s group   (4 + 4 outputs)
    const int ty  = tid >> 4;    // co group  (8 outputs = 4 packed pairs)

    __shared__ __align__(16) float ws[48 * 130];   // [ci*3+t][co], stride 130 (R13 proven)
    __shared__ __align__(16) float ins[16][132];   // [ci][sp], sp in 0..129 (halo 130)

    u64 accp[4][2][4];
    #pragma unroll
    for (int vp = 0; vp < 4; vp++)
        #pragma unroll
        for (int h = 0; h < 2; h++)
            #pragma unroll
            for (int u = 0; u < 4; u++) accp[vp][h][u] = 0ULL;

    const float* in_b = in + (size_t)b * CI * SLEN;

    for (int ci0 = 0; ci0 < CI; ci0 += 16) {
        __syncthreads();
        for (int i = tid; i < 16 * 130; i += 256) {
            int ci = i / 130, sp = i - ci * 130;
            int s = s_tile - 1 + sp;
            float v = 0.f;
            if (s >= 0 && s < SLEN) v = in_b[(size_t)(ci0 + ci) * SLEN + s];
            ins[ci][sp] = v;
        }
        for (int i = tid; i < 128 * 48; i += 256) {
            int co = i / 48, j = i - co * 48;            // j = ci_local*3 + t
            ws[j * 130 + co] = w[(size_t)(co_base + co) * (CI * 3) + (size_t)ci0 * 3 + j];
        }
        __syncthreads();

        #pragma unroll
        for (int ci = 0; ci < 16; ci++) {
            float xv[6], xw[6];
            #pragma unroll
            for (int u = 0; u < 6; u++) xv[u] = ins[ci][tx * 4 + u];
            #pragma unroll
            for (int u = 0; u < 6; u++) xw[u] = ins[ci][64 + tx * 4 + u];
            #pragma unroll
            for (int t = 0; t < 3; t++) {
                const float* wrow = &ws[(ci * 3 + t) * 130 + ty * 8];
                u64 w0 = *reinterpret_cast<const u64*>(wrow + 0);   // (wv[0],wv[1])
                u64 w1 = *reinterpret_cast<const u64*>(wrow + 2);
                u64 w2 = *reinterpret_cast<const u64*>(wrow + 4);
                u64 w3 = *reinterpret_cast<const u64*>(wrow + 6);
                #pragma unroll
                for (int u = 0; u < 4; u++) {
                    u64 xb = bcast2(xv[u + t]);
                    fma2(accp[0][0][u], w0, xb);
                    fma2(accp[1][0][u], w1, xb);
                    fma2(accp[2][0][u], w2, xb);
                    fma2(accp[3][0][u], w3, xb);
                }
                #pragma unroll
                for (int u = 0; u < 4; u++) {
                    u64 xb = bcast2(xw[u + t]);
                    fma2(accp[0][1][u], w0, xb);
                    fma2(accp[1][1][u], w1, xb);
                    fma2(accp[2][1][u], w2, xb);
                    fma2(accp[3][1][u], w3, xb);
                }
            }
        }
    }

    #pragma unroll
    for (int vp = 0; vp < 4; vp++) {
        int co0 = co_base + ty * 8 + 2 * vp;
        float bb0 = bias[co0];
        float bb1 = bias[co0 + 1];
        #pragma unroll
        for (int h = 0; h < 2; h++) {
            #pragma unroll
            for (int u = 0; u < 4; u++) {
                float a0, a1;
                unpack2(accp[vp][h][u], a0, a1);
                int s = s_tile + h * 64 + tx * 4 + u;
                float r0 = a0 + bb0;
                float r1 = a1 + bb1;
                if (RELU) {
                    r0 = (r0 >= 0.f) ? r0 : 0.2f * r0;
                    r1 = (r1 >= 0.f) ? r1 : 0.2f * r1;
                }
                out[((size_t)b * CO + co0) * SLEN + s]     = r0;
                out[((size_t)b * CO + co0 + 1) * SLEN + s] = r1;
            }
        }
    }
}

// ------- VQ: bit-exact argmin (round-13 proven), f32x2-packed dots -------
__global__ __launch_bounds__(256) void vq_k(const float* __restrict__ cb,
                                            float* __restrict__ out_idx) {
    __shared__ __align__(16) float4 cbs[64 * 32];   // 64 codes x 128 floats = 32 KB
    __shared__ float  c2s[64];

    int gp = blockIdx.x * 256 + threadIdx.x;     // global position in [0, B*S)
    int b = gp >> 11;
    int s = gp & (SLEN - 1);

    const float* zb = g_z + (size_t)b * DDIM * SLEN + s;
    u64 zp[64];
    float z2 = 0.f;
    #pragma unroll
    for (int q = 0; q < 64; q++) {
        float a0 = zb[(size_t)(2 * q) * SLEN];
        float a1 = zb[(size_t)(2 * q + 1) * SLEN];
        zp[q] = pack2(a0, a1);
        z2 += a0 * a0;
        z2 += a1 * a1;
    }

    float best = CUDART_INF_F;
    int bi = 0;
    const float4* cb4 = reinterpret_cast<const float4*>(cb);

    for (int kc = 0; kc < KCODE; kc += 64) {
        __syncthreads();
        #pragma unroll
        for (int i = threadIdx.x; i < 64 * 32; i += 256)
            cbs[i] = cb4[kc * 32 + i];
        if (threadIdx.x < 64) c2s[threadIdx.x] = g_c2[kc + threadIdx.x];
        __syncthreads();

        for (int kk = 0; kk < 64; kk++) {
            const u64* cp = reinterpret_cast<const u64*>(&cbs[kk * 32]);
            u64 d01 = 0ULL, d23 = 0ULL;     // lanes: (d0,d1), (d2,d3)
            #pragma unroll
            for (int q = 0; q < 32; q++) {
                fma2(d01, cp[2 * q],     zp[2 * q]);
                fma2(d23, cp[2 * q + 1], zp[2 * q + 1]);
            }
            float d0, d1, d2, d3;
            unpack2(d01, d0, d1);
            unpack2(d23, d2, d3);
            float dist = z2 + c2s[kk] - 2.f * ((d0 + d1) + (d2 + d3));
            if (dist < best) { best = dist; bi = kc + kk; }
        }
    }

    out_idx[gp] = (float)bi;

    const float* cc = cb + (size_t)bi * DDIM;
    float4* zq = reinterpret_cast<float4*>(g_zq + (size_t)gp * DDIM);
    float qs = 0.f;
    #pragma unroll
    for (int q = 0; q < 64; q++) {
        float a0, a1;
        unpack2(zp[q], a0, a1);
        float df0 = a0 - cc[2 * q];
        qs += df0 * df0;
        float df1 = a1 - cc[2 * q + 1];
        qs += df1 * df1;
    }
    #pragma unroll
    for (int q = 0; q < 32; q++) zq[q] = __ldg(reinterpret_cast<const float4*>(cc) + q);

    __shared__ float red[256];
    red[threadIdx.x] = qs;
    __syncthreads();
    for (int off = 128; off > 0; off >>= 1) {
        if (threadIdx.x < off) red[threadIdx.x] += red[threadIdx.x + off];
        __syncthreads();
    }
    if (threadIdx.x == 0) atomicAdd(&g_acc[0], (double)red[0]);
}

// weight prep: [CO][ci*3+t] fp32 -> K-major [CO][t*CI+ci] bf16 hi/lo
template<int CO, int CI>
__global__ __launch_bounds__(256) void wprep_k(const float* __restrict__ w,
                                               __nv_bfloat16* __restrict__ wh,
                                               __nv_bfloat16* __restrict__ wl) {
    int idx = blockIdx.x * 256 + threadIdx.x;        // over CO*3*CI
    int co = idx / (3 * CI);
    int r  = idx - co * (3 * CI);                    // = t*CI + ci
    int t  = r / CI;
    int ci = r - t * CI;
    float v = w[(size_t)co * 3 * CI + (size_t)ci * 3 + t];
    __nv_bfloat16 h = __float2bfloat16_rn(v);
    wh[idx] = h;
    wl[idx] = __float2bfloat16_rn(v - __bfloat162float(h));
}

// ============ bf16 hi/lo 3-term HMMA conv (round-11 proven): CI -> CO ============
template<int CI, int CO, bool RELU>
__global__ __launch_bounds__(256, 2) void conv_mma_k(const float* __restrict__ in,
                                                     const __nv_bfloat16* __restrict__ wh,
                                                     const __nv_bfloat16* __restrict__ wl,
                                                     const float* __restrict__ bias,
                                                     float* __restrict__ out) {
    constexpr int KTOT = 3 * CI;
    constexpr int NCH  = KTOT / 32;
    constexpr int RSTR = 80;                 // bytes per smem row (32 bf16 + 16 pad)

    __shared__ __align__(16) char smem_[4 * 128 * RSTR];   // 40 KB
    char* Ah = smem_;
    char* Al = smem_ + 128 * RSTR;
    char* Bh = smem_ + 2 * 128 * RSTR;
    char* Bl = smem_ + 3 * 128 * RSTR;

    const int tid  = threadIdx.x;
    const int lane = tid & 31;
    const int wid  = tid >> 5;
    const int wm   = wid & 1;                // 2 warps over co
    const int wn   = wid >> 1;               // 4 warps over p
    const int g    = lane >> 2;              // group id 0..7
    const int t4   = lane & 3;               // thread-in-group 0..3

    const int bs_base = blockIdx.x * 128;
    const int co_base = blockIdx.y * 128;
    const int s_in_b0 = bs_base & (SLEN - 1);

    float acc[4][4][4];
    #pragma unroll
    for (int i = 0; i < 4; i++)
        #pragma unroll
        for (int j = 0; j < 4; j++)
            #pragma unroll
            for (int e = 0; e < 4; e++) acc[i][j][e] = 0.f;

    for (int kc = 0; kc < NCH; kc++) {
        const int t   = (kc * 32) / CI;       // tap (chunk never crosses taps; CI%32==0)
        const int ci0 = (kc * 32) % CI;
        __syncthreads();

        #pragma unroll
        for (int j = 0; j < 2; j++) {
            int idx = tid + 256 * j;          // 512 uint4
            int row = idx >> 2, q = idx & 3;
            size_t src = (size_t)(co_base + row) * KTOT + kc * 32;
            uint4 vh = reinterpret_cast<const uint4*>(wh + src)[q];
            uint4 vl = reinterpret_cast<const uint4*>(wl + src)[q];
            *reinterpret_cast<uint4*>(Ah + row * RSTR + q * 16) = vh;
            *reinterpret_cast<uint4*>(Al + row * RSTR + q * 16) = vl;
        }
        #pragma unroll
        for (int j = 0; j < 4; j++) {
            int idx = tid + 256 * j;          // 1024 float4
            int row = idx >> 3, q = idx & 7;
            int sb = s_in_b0 + row + t - 1;
            float4 v = make_float4(0.f, 0.f, 0.f, 0.f);
            if (sb >= 0 && sb < SLEN)
                v = *reinterpret_cast<const float4*>(
                        in + (size_t)(bs_base + row + t - 1) * CI + ci0 + 4 * q);
            float r0, r1, r2, r3;
            uint32_t hp0 = pack_hi(v.x, v.y, r0, r1);
            uint32_t hp1 = pack_hi(v.z, v.w, r2, r3);
            *reinterpret_cast<uint2*>(Bh + row * RSTR + q * 8) = make_uint2(hp0, hp1);
            *reinterpret_cast<uint2*>(Bl + row * RSTR + q * 8) =
                make_uint2(pack_lo(r0, r1), pack_lo(r2, r3));
        }
        __syncthreads();

        #pragma unroll
        for (int ks = 0; ks < 2; ks++) {
            const int kb = ks * 32 + t4 * 4;  // byte offset of this thread's k pair
            uint32_t bh[4][2], bl[4][2];
            #pragma unroll
            for (int nf = 0; nf < 4; nf++) {
                int nrow = wn * 32 + nf * 8 + g;
                bh[nf][0] = *reinterpret_cast<uint32_t*>(Bh + nrow * RSTR + kb);
                bh[nf][1] = *reinterpret_cast<uint32_t*>(Bh + nrow * RSTR + kb + 16);
                bl[nf][0] = *reinterpret_cast<uint32_t*>(Bl + nrow * RSTR + kb);
                bl[nf][1] = *reinterpret_cast<uint32_t*>(Bl + nrow * RSTR + kb + 16);
            }
            #pragma unroll
            for (int mf = 0; mf < 4; mf++) {
                int mrow = wm * 64 + mf * 16 + g;
                uint32_t ah[4], al[4];
                ah[0] = *reinterpret_cast<uint32_t*>(Ah + mrow * RSTR + kb);
                ah[1] = *reinterpret_cast<uint32_t*>(Ah + (mrow + 8) * RSTR + kb);
                ah[2] = *reinterpret_cast<uint32_t*>(Ah + mrow * RSTR + kb + 16);
                ah[3] = *reinterpret_cast<uint32_t*>(Ah + (mrow + 8) * RSTR + kb + 16);
                al[0] = *reinterpret_cast<uint32_t*>(Al + mrow * RSTR + kb);
                al[1] = *reinterpret_cast<uint32_t*>(Al + (mrow + 8) * RSTR + kb);
                al[2] = *reinterpret_cast<uint32_t*>(Al + mrow * RSTR + kb + 16);
                al[3] = *reinterpret_cast<uint32_t*>(Al + (mrow + 8) * RSTR + kb + 16);
                #pragma unroll
                for (int nf = 0; nf < 4; nf++) {
                    mma16816(acc[mf][nf], ah, bh[nf]);
                    mma16816(acc[mf][nf], ah, bl[nf]);
                    mma16816(acc[mf][nf], al, bh[nf]);
                }
            }
        }
    }

    #pragma unroll
    for (int mf = 0; mf < 4; mf++) {
        int co0 = co_base + wm * 64 + mf * 16 + g;
        float bb0 = bias[co0];
        float bb1 = bias[co0 + 8];
        #pragma unroll
        for (int nf = 0; nf < 4; nf++) {
            int p = bs_base + wn * 32 + nf * 8 + t4 * 2;
            #pragma unroll
            for (int e = 0; e < 2; e++) {
                float v0 = acc[mf][nf][e] + bb0;       // row g,   col t4*2+e
                float v1 = acc[mf][nf][2 + e] + bb1;   // row g+8, col t4*2+e
                if (RELU) {
                    v0 = (v0 >= 0.f) ? v0 : 0.2f * v0;
                    v1 = (v1 >= 0.f) ? v1 : 0.2f * v1;
                }
                out[(size_t)(p + e) * CO + co0]     = v0;
                out[(size_t)(p + e) * CO + co0 + 8] = v1;
            }
        }
    }
}

// ---------------- decoder conv3: H -> 1 (channel-last input) + recon loss ----
__global__ __launch_bounds__(256) void dec3_k(const float* __restrict__ hin,
                                              const float* __restrict__ w,
                                              const float* __restrict__ bias,
                                              const float* __restrict__ x,
                                              float* __restrict__ xrec) {
    __shared__ float ws[HDIM * 3];
    for (int i = threadIdx.x; i < HDIM * 3; i += 256) ws[i] = w[i];
    __syncthreads();

    int wid = threadIdx.x >> 5, lane = threadIdx.x & 31;
    int p = blockIdx.x * 8 + wid;     // global position
    int s = p & (SLEN - 1);

    float acc = 0.f;
    #pragma unroll
    for (int t = 0; t < 3; t++) {
        int sb = s + t - 1;
        if (sb < 0 || sb >= SLEN) continue;
        const float4* r = reinterpret_cast<const float4*>(hin + (size_t)(p + t - 1) * HDIM);
        #pragma unroll
        for (int q = 0; q < 2; q++) {
            float4 v = r[lane * 2 + q];
            int c0 = lane * 8 + q * 4;
            acc += v.x * ws[(c0+0)*3+t] + v.y * ws[(c0+1)*3+t]
                 + v.z * ws[(c0+2)*3+t] + v.w * ws[(c0+3)*3+t];
        }
    }
    #pragma unroll
    for (int off = 16; off > 0; off >>= 1)
        acc += __shfl_xor_sync(0xFFFFFFFFu, acc, off);

    __shared__ float wsum[8];
    if (lane == 0) {
        float a = acc + bias[0];
        xrec[p] = a;
        float diff = x[p] - a;
        wsum[wid] = diff * diff;
    }
    __syncthreads();
    if (threadIdx.x == 0) {
        float s8 = 0.f;
        #pragma unroll
        for (int i = 0; i < 8; i++) s8 += wsum[i];
        atomicAdd(&g_acc[1], (double)s8);
    }
}

// ---------------- finalize losses ----------------
__global__ void fin_k(float* __restrict__ out) {
    double qsum = g_acc[0];
    double rsum = g_acc[1];
    float qm    = (float)(qsum / ((double)BATCH * SLEN * DDIM));
    float recon = (float)(rsum / ((double)BATCH * SLEN));
    float vq    = qm * 0.05f;
    float com   = qm * 0.15f;
    size_t base = (size_t)2 * BATCH * SLEN;
    out[base + 0] = recon + vq + com;
    out[base + 1] = recon;
    out[base + 2] = vq;
    out[base + 3] = com;
}

// ---------------- launch ----------------
extern "C" void kernel_launch(void* const* d_in, const int* in_sizes, int n_in,
                              void* d_out, int out_size) {
    const float* x   = (const float*)d_in[0];
    const float* cb  = (const float*)d_in[1];
    const float* ew1 = (const float*)d_in[2];
    const float* eb1 = (const float*)d_in[3];
    const float* ew2 = (const float*)d_in[4];
    const float* eb2 = (const float*)d_in[5];
    const float* ew3 = (const float*)d_in[6];
    const float* eb3 = (const float*)d_in[7];
    const float* dw1 = (const float*)d_in[8];
    const float* db1 = (const float*)d_in[9];
    const float* dw2 = (const float*)d_in[10];
    const float* db2 = (const float*)d_in[11];
    const float* dw3 = (const float*)d_in[12];
    const float* db3 = (const float*)d_in[13];
    float* out = (float*)d_out;

    float *h1, *h2, *z, *zq, *d1, *d2;
    __nv_bfloat16 *wh, *wl;
    cudaGetSymbolAddress((void**)&h1, g_h1);
    cudaGetSymbolAddress((void**)&h2, g_h2);
    cudaGetSymbolAddress((void**)&z,  g_z);
    cudaGetSymbolAddress((void**)&zq, g_zq);
    cudaGetSymbolAddress((void**)&d1, g_d1);
    cudaGetSymbolAddress((void**)&d2, g_d2);
    cudaGetSymbolAddress((void**)&wh, g_wh);
    cudaGetSymbolAddress((void**)&wl, g_wl);

    init_k<<<1, 32>>>();
    c2_k<<<2, 256>>>(cb);

    // ---------- encoder: fp32 SIMT path, f32x2-packed (bit-identical values) ----------
    enc1_k<<<(BATCH * HDIM * SLEN) / 256, 256>>>(x, ew1, eb1);

    dim3 g2(SLEN / 128, HDIM / 128, BATCH);
    conv_k<HDIM, HDIM, true><<<g2, 256>>>(h1, ew2, eb2, h2);

    dim3 g3(SLEN / 128, DDIM / 128, BATCH);
    conv_k<HDIM, DDIM, false><<<g3, 256>>>(h2, ew3, eb3, z);

    // ---------- VQ: bit-exact argmin, f32x2-packed dots ----------
    vq_k<<<(BATCH * SLEN) / 256, 256>>>(cb, out + (size_t)BATCH * SLEN);

    // ---------- decoder: bf16 hi/lo 3-term HMMA (round-11 proven) ----------
    const int STILES = (BATCH * SLEN) / 128;   // 512

    wprep_k<HDIM, DDIM><<<(HDIM * 3 * DDIM) / 256, 256>>>(dw1, wh, wl);
    conv_mma_k<DDIM, HDIM, true><<<dim3(STILES, HDIM / 128), 256>>>(
        zq, wh, wl, db1, d1);

    wprep_k<HDIM, HDIM><<<(HDIM * 3 * HDIM) / 256, 256>>>(dw2, wh, wl);
    conv_mma_k<HDIM, HDIM, true><<<dim3(STILES, HDIM / 128), 256>>>(
        d1, wh, wl, db2, d2);

    dec3_k<<<(BATCH * SLEN) / 8, 256>>>(d2, dw3, db3, x, out);

    fin_k<<<1, 1>>>(out);
}

// round 16
// speedup vs baseline: 1.7237x; 1.0290x over previous
#include <cuda_runtime.h>
#include <cuda_bf16.h>
#include <cstdint>
#include <math_constants.h>

#define BATCH 32
#define SLEN  2048
#define DDIM  128
#define HDIM  256
#define KCODE 512

// ---------------- scratch (static device globals; no allocation) ----------------
__device__ float g_h1[(size_t)BATCH * HDIM * SLEN];   // 64 MB  enc, channel-first
__device__ float g_h2[(size_t)BATCH * HDIM * SLEN];   // 64 MB  enc, channel-first
__device__ float g_z [(size_t)BATCH * DDIM * SLEN];   // 32 MB  channel-first
__device__ float g_zq[(size_t)BATCH * SLEN * DDIM];   // 32 MB  channel-last (feeds MMA dec)
__device__ float g_d1[(size_t)BATCH * SLEN * HDIM];   // 64 MB  dec1 out channel-last
__device__ float g_d2[(size_t)BATCH * SLEN * HDIM];   // 64 MB  dec2 out channel-last
__device__ __nv_bfloat16 g_wh[HDIM * 3 * HDIM];       // K-major weight hi (bf16)
__device__ __nv_bfloat16 g_wl[HDIM * 3 * HDIM];       // K-major weight lo (bf16)
__device__ float g_c2[KCODE];
__device__ double g_acc[2];                            // [0]=sum min dist, [1]=recon SSE

// ---------------- helpers ----------------
typedef unsigned long long u64;

__device__ __forceinline__ u64 pack2(float lo, float hi) {
    u64 r;
    asm("mov.b64 %0, {%1, %2};" : "=l"(r) : "f"(lo), "f"(hi));
    return r;
}
__device__ __forceinline__ u64 bcast2(float v) {
    u64 r;
    asm("mov.b64 %0, {%1, %1};" : "=l"(r) : "f"(v));
    return r;
}
__device__ __forceinline__ void unpack2(u64 p, float& lo, float& hi) {
    asm("mov.b64 {%0, %1}, %2;" : "=f"(lo), "=f"(hi) : "l"(p));
}
// packed dual fp32 FMA: per-lane identical to scalar FFMA (rn, fused)
__device__ __forceinline__ void fma2(u64& d, u64 a, u64 b) {
    asm("fma.rn.f32x2 %0, %1, %2, %0;" : "+l"(d) : "l"(a), "l"(b));
}

// cp.async 4B with zero-fill when pred==false (src-size 0)
__device__ __forceinline__ uint32_t smem_u32(const void* p) {
    return (uint32_t)__cvta_generic_to_shared(p);
}
__device__ __forceinline__ void cpa4(uint32_t dst, const float* src, bool ok) {
    int sz = ok ? 4 : 0;
    asm volatile("cp.async.ca.shared.global [%0], [%1], 4, %2;"
                 :: "r"(dst), "l"(src), "r"(sz));
}

__device__ __forceinline__ uint32_t pack_hi(float v0, float v1, float& r0, float& r1) {
    __nv_bfloat16 h0 = __float2bfloat16_rn(v0);
    __nv_bfloat16 h1 = __float2bfloat16_rn(v1);
    r0 = v0 - __bfloat162float(h0);
    r1 = v1 - __bfloat162float(h1);
    return ((uint32_t)__bfloat16_as_ushort(h1) << 16) | (uint32_t)__bfloat16_as_ushort(h0);
}
__device__ __forceinline__ uint32_t pack_lo(float r0, float r1) {
    __nv_bfloat16 l0 = __float2bfloat16_rn(r0);
    __nv_bfloat16 l1 = __float2bfloat16_rn(r1);
    return ((uint32_t)__bfloat16_as_ushort(l1) << 16) | (uint32_t)__bfloat16_as_ushort(l0);
}

__device__ __forceinline__ void mma16816(float* d, const uint32_t* a, const uint32_t* b) {
    asm volatile(
        "mma.sync.aligned.m16n8k16.row.col.f32.bf16.bf16.f32 "
        "{%0,%1,%2,%3}, {%4,%5,%6,%7}, {%8,%9}, {%0,%1,%2,%3};"
        : "+f"(d[0]), "+f"(d[1]), "+f"(d[2]), "+f"(d[3])
        : "r"(a[0]), "r"(a[1]), "r"(a[2]), "r"(a[3]), "r"(b[0]), "r"(b[1]));
}

// ---------------- init ----------------
__global__ void init_k() {
    if (threadIdx.x < 2) g_acc[threadIdx.x] = 0.0;
}

// ---------------- codebook norms ----------------
__global__ void c2_k(const float* __restrict__ cb) {
    int k = blockIdx.x * blockDim.x + threadIdx.x;
    if (k < KCODE) {
        const float* r = cb + (size_t)k * DDIM;
        float s = 0.f;
        #pragma unroll 8
        for (int d = 0; d < DDIM; d++) s += r[d] * r[d];
        g_c2[k] = s;
    }
}

// ---------------- encoder conv1: 1 -> H, k=3, SAME, lrelu (round-1 proven) ---
__global__ __launch_bounds__(256) void enc1_k(const float* __restrict__ x,
                                              const float* __restrict__ w,
                                              const float* __restrict__ bias) {
    size_t idx = (size_t)blockIdx.x * blockDim.x + threadIdx.x;   // over B*H*S
    int s = idx & (SLEN - 1);
    int c = (idx >> 11) & (HDIM - 1);
    int b = idx >> 19;
    const float* xb = x + (size_t)b * SLEN;
    float v = bias[c];
    float w0 = w[c*3+0], w1 = w[c*3+1], w2 = w[c*3+2];
    if (s > 0)        v += w0 * xb[s-1];
    v += w1 * xb[s];
    if (s < SLEN - 1) v += w2 * xb[s+1];
    g_h1[idx] = (v >= 0.f) ? v : 0.2f * v;
}

// ------------ SIMT fp32 conv, f32x2 (R15 compute), cp.async double-buffered ------------
// Each thread computes 8 co x 8 s (two s-groups 64 apart, same weight regs).
#define WS_SZ  (48 * 130)
#define INS_SZ (16 * 132)
#define BUF_SZ (WS_SZ + INS_SZ)
template<int CI, int CO, bool RELU>
__global__ __launch_bounds__(256) void conv_k(const float* __restrict__ in,
                                              const float* __restrict__ w,
                                              const float* __restrict__ bias,
                                              float* __restrict__ out) {
    const int s_tile  = blockIdx.x * 128;
    const int co_base = blockIdx.y * 128;
    const int b       = blockIdx.z;
    const int tid = threadIdx.x;
    const int tx  = tid & 15;    // s group   (4 + 4 outputs)
    const int ty  = tid >> 4;    // co group  (8 outputs = 4 packed pairs)

    extern __shared__ __align__(16) float dynsm[];
    const float* in_b = in + (size_t)b * CI * SLEN;
    const int NCHUNK = CI / 16;

    u64 accp[4][2][4];
    #pragma unroll
    for (int vp = 0; vp < 4; vp++)
        #pragma unroll
        for (int h = 0; h < 2; h++)
            #pragma unroll
            for (int u = 0; u < 4; u++) accp[vp][h][u] = 0ULL;

    // stage one k-chunk into buffer `bf` via cp.async
    auto load_chunk = [&](int ci0, int bf) {
        float* wsb  = dynsm + bf * BUF_SZ;
        float* insb = wsb + WS_SZ;
        for (int i = tid; i < 16 * 130; i += 256) {
            int ci = i / 130, sp = i - ci * 130;
            int s = s_tile - 1 + sp;
            bool ok = (s >= 0 && s < SLEN);
            const float* src = ok ? (in_b + (size_t)(ci0 + ci) * SLEN + s) : in_b;
            cpa4(smem_u32(insb + ci * 132 + sp), src, ok);
        }
        for (int i = tid; i < 128 * 48; i += 256) {
            int co = i / 48, j = i - co * 48;            // j = ci_local*3 + t
            cpa4(smem_u32(wsb + j * 130 + co),
                 w + (size_t)(co_base + co) * (CI * 3) + (size_t)ci0 * 3 + j, true);
        }
    };

    load_chunk(0, 0);
    asm volatile("cp.async.commit_group;" ::: "memory");

    for (int c = 0; c < NCHUNK; c++) {
        if (c + 1 < NCHUNK) {
            load_chunk((c + 1) * 16, (c + 1) & 1);
            asm volatile("cp.async.commit_group;" ::: "memory");
            asm volatile("cp.async.wait_group 1;" ::: "memory");
        } else {
            asm volatile("cp.async.wait_group 0;" ::: "memory");
        }
        __syncthreads();

        const float* ws  = dynsm + (c & 1) * BUF_SZ;
        const float* ins = ws + WS_SZ;

        #pragma unroll
        for (int ci = 0; ci < 16; ci++) {
            float xv[6], xw[6];
            #pragma unroll
            for (int u = 0; u < 6; u++) xv[u] = ins[ci * 132 + tx * 4 + u];
            #pragma unroll
            for (int u = 0; u < 6; u++) xw[u] = ins[ci * 132 + 64 + tx * 4 + u];
            #pragma unroll
            for (int t = 0; t < 3; t++) {
                const float* wrow = &ws[(ci * 3 + t) * 130 + ty * 8];
                u64 w0 = *reinterpret_cast<const u64*>(wrow + 0);   // (wv[0],wv[1])
                u64 w1 = *reinterpret_cast<const u64*>(wrow + 2);
                u64 w2 = *reinterpret_cast<const u64*>(wrow + 4);
                u64 w3 = *reinterpret_cast<const u64*>(wrow + 6);
                #pragma unroll
                for (int u = 0; u < 4; u++) {
                    u64 xb = bcast2(xv[u + t]);
                    fma2(accp[0][0][u], w0, xb);
                    fma2(accp[1][0][u], w1, xb);
                    fma2(accp[2][0][u], w2, xb);
                    fma2(accp[3][0][u], w3, xb);
                }
                #pragma unroll
                for (int u = 0; u < 4; u++) {
                    u64 xb = bcast2(xw[u + t]);
                    fma2(accp[0][1][u], w0, xb);
                    fma2(accp[1][1][u], w1, xb);
                    fma2(accp[2][1][u], w2, xb);
                    fma2(accp[3][1][u], w3, xb);
                }
            }
        }
        __syncthreads();   // protect buf (c&1) from next prefetch overwrite
    }

    #pragma unroll
    for (int vp = 0; vp < 4; vp++) {
        int co0 = co_base + ty * 8 + 2 * vp;
        float bb0 = bias[co0];
        float bb1 = bias[co0 + 1];
        #pragma unroll
        for (int h = 0; h < 2; h++) {
            #pragma unroll
            for (int u = 0; u < 4; u++) {
                float a0, a1;
                unpack2(accp[vp][h][u], a0, a1);
                int s = s_tile + h * 64 + tx * 4 + u;
                float r0 = a0 + bb0;
                float r1 = a1 + bb1;
                if (RELU) {
                    r0 = (r0 >= 0.f) ? r0 : 0.2f * r0;
                    r1 = (r1 >= 0.f) ? r1 : 0.2f * r1;
                }
                out[((size_t)b * CO + co0) * SLEN + s]     = r0;
                out[((size_t)b * CO + co0 + 1) * SLEN + s] = r1;
            }
        }
    }
}

// ------- VQ: bit-exact argmin (round-13 proven), f32x2-packed dots -------
__global__ __launch_bounds__(256) void vq_k(const float* __restrict__ cb,
                                            float* __restrict__ out_idx) {
    __shared__ __align__(16) float4 cbs[64 * 32];   // 64 codes x 128 floats = 32 KB
    __shared__ float  c2s[64];

    int gp = blockIdx.x * 256 + threadIdx.x;     // global position in [0, B*S)
    int b = gp >> 11;
    int s = gp & (SLEN - 1);

    const float* zb = g_z + (size_t)b * DDIM * SLEN + s;
    u64 zp[64];
    float z2 = 0.f;
    #pragma unroll
    for (int q = 0; q < 64; q++) {
        float a0 = zb[(size_t)(2 * q) * SLEN];
        float a1 = zb[(size_t)(2 * q + 1) * SLEN];
        zp[q] = pack2(a0, a1);
        z2 += a0 * a0;
        z2 += a1 * a1;
    }

    float best = CUDART_INF_F;
    int bi = 0;
    const float4* cb4 = reinterpret_cast<const float4*>(cb);

    for (int kc = 0; kc < KCODE; kc += 64) {
        __syncthreads();
        #pragma unroll
        for (int i = threadIdx.x; i < 64 * 32; i += 256)
            cbs[i] = cb4[kc * 32 + i];
        if (threadIdx.x < 64) c2s[threadIdx.x] = g_c2[kc + threadIdx.x];
        __syncthreads();

        for (int kk = 0; kk < 64; kk++) {
            const u64* cp = reinterpret_cast<const u64*>(&cbs[kk * 32]);
            u64 d01 = 0ULL, d23 = 0ULL;     // lanes: (d0,d1), (d2,d3)
            #pragma unroll
            for (int q = 0; q < 32; q++) {
                fma2(d01, cp[2 * q],     zp[2 * q]);
                fma2(d23, cp[2 * q + 1], zp[2 * q + 1]);
            }
            float d0, d1, d2, d3;
            unpack2(d01, d0, d1);
            unpack2(d23, d2, d3);
            float dist = z2 + c2s[kk] - 2.f * ((d0 + d1) + (d2 + d3));
            if (dist < best) { best = dist; bi = kc + kk; }
        }
    }

    out_idx[gp] = (float)bi;

    const float* cc = cb + (size_t)bi * DDIM;
    float4* zq = reinterpret_cast<float4*>(g_zq + (size_t)gp * DDIM);
    float qs = 0.f;
    #pragma unroll
    for (int q = 0; q < 64; q++) {
        float a0, a1;
        unpack2(zp[q], a0, a1);
        float df0 = a0 - cc[2 * q];
        qs += df0 * df0;
        float df1 = a1 - cc[2 * q + 1];
        qs += df1 * df1;
    }
    #pragma unroll
    for (int q = 0; q < 32; q++) zq[q] = __ldg(reinterpret_cast<const float4*>(cc) + q);

    __shared__ float red[256];
    red[threadIdx.x] = qs;
    __syncthreads();
    for (int off = 128; off > 0; off >>= 1) {
        if (threadIdx.x < off) red[threadIdx.x] += red[threadIdx.x + off];
        __syncthreads();
    }
    if (threadIdx.x == 0) atomicAdd(&g_acc[0], (double)red[0]);
}

// weight prep: [CO][ci*3+t] fp32 -> K-major [CO][t*CI+ci] bf16 hi/lo
template<int CO, int CI>
__global__ __launch_bounds__(256) void wprep_k(const float* __restrict__ w,
                                               __nv_bfloat16* __restrict__ wh,
                                               __nv_bfloat16* __restrict__ wl) {
    int idx = blockIdx.x * 256 + threadIdx.x;        // over CO*3*CI
    int co = idx / (3 * CI);
    int r  = idx - co * (3 * CI);                    // = t*CI + ci
    int t  = r / CI;
    int ci = r - t * CI;
    float v = w[(size_t)co * 3 * CI + (size_t)ci * 3 + t];
    __nv_bfloat16 h = __float2bfloat16_rn(v);
    wh[idx] = h;
    wl[idx] = __float2bfloat16_rn(v - __bfloat162float(h));
}

// ============ bf16 hi/lo 3-term HMMA conv (round-11 proven): CI -> CO ============
template<int CI, int CO, bool RELU>
__global__ __launch_bounds__(256, 2) void conv_mma_k(const float* __restrict__ in,
                                                     const __nv_bfloat16* __restrict__ wh,
                                                     const __nv_bfloat16* __restrict__ wl,
                                                     const float* __restrict__ bias,
                                                     float* __restrict__ out) {
    constexpr int KTOT = 3 * CI;
    constexpr int NCH  = KTOT / 32;
    constexpr int RSTR = 80;                 // bytes per smem row (32 bf16 + 16 pad)

    __shared__ __align__(16) char smem_[4 * 128 * RSTR];   // 40 KB
    char* Ah = smem_;
    char* Al = smem_ + 128 * RSTR;
    char* Bh = smem_ + 2 * 128 * RSTR;
    char* Bl = smem_ + 3 * 128 * RSTR;

    const int tid  = threadIdx.x;
    const int lane = tid & 31;
    const int wid  = tid >> 5;
    const int wm   = wid & 1;                // 2 warps over co
    const int wn   = wid >> 1;               // 4 warps over p
    const int g    = lane >> 2;              // group id 0..7
    const int t4   = lane & 3;               // thread-in-group 0..3

    const int bs_base = blockIdx.x * 128;
    const int co_base = blockIdx.y * 128;
    const int s_in_b0 = bs_base & (SLEN - 1);

    float acc[4][4][4];
    #pragma unroll
    for (int i = 0; i < 4; i++)
        #pragma unroll
        for (int j = 0; j < 4; j++)
            #pragma unroll
            for (int e = 0; e < 4; e++) acc[i][j][e] = 0.f;

    for (int kc = 0; kc < NCH; kc++) {
        const int t   = (kc * 32) / CI;       // tap (chunk never crosses taps; CI%32==0)
        const int ci0 = (kc * 32) % CI;
        __syncthreads();

        #pragma unroll
        for (int j = 0; j < 2; j++) {
            int idx = tid + 256 * j;          // 512 uint4
            int row = idx >> 2, q = idx & 3;
            size_t src = (size_t)(co_base + row) * KTOT + kc * 32;
            uint4 vh = reinterpret_cast<const uint4*>(wh + src)[q];
            uint4 vl = reinterpret_cast<const uint4*>(wl + src)[q];
            *reinterpret_cast<uint4*>(Ah + row * RSTR + q * 16) = vh;
            *reinterpret_cast<uint4*>(Al + row * RSTR + q * 16) = vl;
        }
        #pragma unroll
        for (int j = 0; j < 4; j++) {
            int idx = tid + 256 * j;          // 1024 float4
            int row = idx >> 3, q = idx & 7;
            int sb = s_in_b0 + row + t - 1;
            float4 v = make_float4(0.f, 0.f, 0.f, 0.f);
            if (sb >= 0 && sb < SLEN)
                v = *reinterpret_cast<const float4*>(
                        in + (size_t)(bs_base + row + t - 1) * CI + ci0 + 4 * q);
            float r0, r1, r2, r3;
            uint32_t hp0 = pack_hi(v.x, v.y, r0, r1);
            uint32_t hp1 = pack_hi(v.z, v.w, r2, r3);
            *reinterpret_cast<uint2*>(Bh + row * RSTR + q * 8) = make_uint2(hp0, hp1);
            *reinterpret_cast<uint2*>(Bl + row * RSTR + q * 8) =
                make_uint2(pack_lo(r0, r1), pack_lo(r2, r3));
        }
        __syncthreads();

        #pragma unroll
        for (int ks = 0; ks < 2; ks++) {
            const int kb = ks * 32 + t4 * 4;  // byte offset of this thread's k pair
            uint32_t bh[4][2], bl[4][2];
            #pragma unroll
            for (int nf = 0; nf < 4; nf++) {
                int nrow = wn * 32 + nf * 8 + g;
                bh[nf][0] = *reinterpret_cast<uint32_t*>(Bh + nrow * RSTR + kb);
                bh[nf][1] = *reinterpret_cast<uint32_t*>(Bh + nrow * RSTR + kb + 16);
                bl[nf][0] = *reinterpret_cast<uint32_t*>(Bl + nrow * RSTR + kb);
                bl[nf][1] = *reinterpret_cast<uint32_t*>(Bl + nrow * RSTR + kb + 16);
            }
            #pragma unroll
            for (int mf = 0; mf < 4; mf++) {
                int mrow = wm * 64 + mf * 16 + g;
                uint32_t ah[4], al[4];
                ah[0] = *reinterpret_cast<uint32_t*>(Ah + mrow * RSTR + kb);
                ah[1] = *reinterpret_cast<uint32_t*>(Ah + (mrow + 8) * RSTR + kb);
                ah[2] = *reinterpret_cast<uint32_t*>(Ah + mrow * RSTR + kb + 16);
                ah[3] = *reinterpret_cast<uint32_t*>(Ah + (mrow + 8) * RSTR + kb + 16);
                al[0] = *reinterpret_cast<uint32_t*>(Al + mrow * RSTR + kb);
                al[1] = *reinterpret_cast<uint32_t*>(Al + (mrow + 8) * RSTR + kb);
                al[2] = *reinterpret_cast<uint32_t*>(Al + mrow * RSTR + kb + 16);
                al[3] = *reinterpret_cast<uint32_t*>(Al + (mrow + 8) * RSTR + kb + 16);
                #pragma unroll
                for (int nf = 0; nf < 4; nf++) {
                    mma16816(acc[mf][nf], ah, bh[nf]);
                    mma16816(acc[mf][nf], ah, bl[nf]);
                    mma16816(acc[mf][nf], al, bh[nf]);
                }
            }
        }
    }

    #pragma unroll
    for (int mf = 0; mf < 4; mf++) {
        int co0 = co_base + wm * 64 + mf * 16 + g;
        float bb0 = bias[co0];
        float bb1 = bias[co0 + 8];
        #pragma unroll
        for (int nf = 0; nf < 4; nf++) {
            int p = bs_base + wn * 32 + nf * 8 + t4 * 2;
            #pragma unroll
            for (int e = 0; e < 2; e++) {
                float v0 = acc[mf][nf][e] + bb0;       // row g,   col t4*2+e
                float v1 = acc[mf][nf][2 + e] + bb1;   // row g+8, col t4*2+e
                if (RELU) {
                    v0 = (v0 >= 0.f) ? v0 : 0.2f * v0;
                    v1 = (v1 >= 0.f) ? v1 : 0.2f * v1;
                }
                out[(size_t)(p + e) * CO + co0]     = v0;
                out[(size_t)(p + e) * CO + co0 + 8] = v1;
            }
        }
    }
}

// ---------------- decoder conv3: H -> 1 (channel-last input) + recon loss ----
__global__ __launch_bounds__(256) void dec3_k(const float* __restrict__ hin,
                                              const float* __restrict__ w,
                                              const float* __restrict__ bias,
                                              const float* __restrict__ x,
                                              float* __restrict__ xrec) {
    __shared__ float ws[HDIM * 3];
    for (int i = threadIdx.x; i < HDIM * 3; i += 256) ws[i] = w[i];
    __syncthreads();

    int wid = threadIdx.x >> 5, lane = threadIdx.x & 31;
    int p = blockIdx.x * 8 + wid;     // global position
    int s = p & (SLEN - 1);

    float acc = 0.f;
    #pragma unroll
    for (int t = 0; t < 3; t++) {
        int sb = s + t - 1;
        if (sb < 0 || sb >= SLEN) continue;
        const float4* r = reinterpret_cast<const float4*>(hin + (size_t)(p + t - 1) * HDIM);
        #pragma unroll
        for (int q = 0; q < 2; q++) {
            float4 v = r[lane * 2 + q];
            int c0 = lane * 8 + q * 4;
            acc += v.x * ws[(c0+0)*3+t] + v.y * ws[(c0+1)*3+t]
                 + v.z * ws[(c0+2)*3+t] + v.w * ws[(c0+3)*3+t];
        }
    }
    #pragma unroll
    for (int off = 16; off > 0; off >>= 1)
        acc += __shfl_xor_sync(0xFFFFFFFFu, acc, off);

    __shared__ float wsum[8];
    if (lane == 0) {
        float a = acc + bias[0];
        xrec[p] = a;
        float diff = x[p] - a;
        wsum[wid] = diff * diff;
    }
    __syncthreads();
    if (threadIdx.x == 0) {
        float s8 = 0.f;
        #pragma unroll
        for (int i = 0; i < 8; i++) s8 += wsum[i];
        atomicAdd(&g_acc[1], (double)s8);
    }
}

// ---------------- finalize losses ----------------
__global__ void fin_k(float* __restrict__ out) {
    double qsum = g_acc[0];
    double rsum = g_acc[1];
    float qm    = (float)(qsum / ((double)BATCH * SLEN * DDIM));
    float recon = (float)(rsum / ((double)BATCH * SLEN));
    float vq    = qm * 0.05f;
    float com   = qm * 0.15f;
    size_t base = (size_t)2 * BATCH * SLEN;
    out[base + 0] = recon + vq + com;
    out[base + 1] = recon;
    out[base + 2] = vq;
    out[base + 3] = com;
}

// ---------------- launch ----------------
static const int CONVK_SMEM = 2 * BUF_SZ * 4;   // 66816 bytes

extern "C" void kernel_launch(void* const* d_in, const int* in_sizes, int n_in,
                              void* d_out, int out_size) {
    const float* x   = (const float*)d_in[0];
    const float* cb  = (const float*)d_in[1];
    const float* ew1 = (const float*)d_in[2];
    const float* eb1 = (const float*)d_in[3];
    const float* ew2 = (const float*)d_in[4];
    const float* eb2 = (const float*)d_in[5];
    const float* ew3 = (const float*)d_in[6];
    const float* eb3 = (const float*)d_in[7];
    const float* dw1 = (const float*)d_in[8];
    const float* db1 = (const float*)d_in[9];
    const float* dw2 = (const float*)d_in[10];
    const float* db2 = (const float*)d_in[11];
    const float* dw3 = (const float*)d_in[12];
    const float* db3 = (const float*)d_in[13];
    float* out = (float*)d_out;

    float *h1, *h2, *z, *zq, *d1, *d2;
    __nv_bfloat16 *wh, *wl;
    cudaGetSymbolAddress((void**)&h1, g_h1);
    cudaGetSymbolAddress((void**)&h2, g_h2);
    cudaGetSymbolAddress((void**)&z,  g_z);
    cudaGetSymbolAddress((void**)&zq, g_zq);
    cudaGetSymbolAddress((void**)&d1, g_d1);
    cudaGetSymbolAddress((void**)&d2, g_d2);
    cudaGetSymbolAddress((void**)&wh, g_wh);
    cudaGetSymbolAddress((void**)&wl, g_wl);

    cudaFuncSetAttribute(conv_k<HDIM, HDIM, true>,
                         cudaFuncAttributeMaxDynamicSharedMemorySize, CONVK_SMEM);
    cudaFuncSetAttribute(conv_k<HDIM, DDIM, false>,
                         cudaFuncAttributeMaxDynamicSharedMemorySize, CONVK_SMEM);

    init_k<<<1, 32>>>();
    c2_k<<<2, 256>>>(cb);

    // ---------- encoder: fp32 SIMT path, f32x2-packed (bit-identical values) ----------
    enc1_k<<<(BATCH * HDIM * SLEN) / 256, 256>>>(x, ew1, eb1);

    dim3 g2(SLEN / 128, HDIM / 128, BATCH);
    conv_k<HDIM, HDIM, true><<<g2, 256, CONVK_SMEM>>>(h1, ew2, eb2, h2);

    dim3 g3(SLEN / 128, DDIM / 128, BATCH);
    conv_k<HDIM, DDIM, false><<<g3, 256, CONVK_SMEM>>>(h2, ew3, eb3, z);

    // ---------- VQ: bit-exact argmin, f32x2-packed dots ----------
    vq_k<<<(BATCH * SLEN) / 256, 256>>>(cb, out + (size_t)BATCH * SLEN);

    // ---------- decoder: bf16 hi/lo 3-term HMMA (round-11 proven) ----------
    const int STILES = (BATCH * SLEN) / 128;   // 512

    wprep_k<HDIM, DDIM><<<(HDIM * 3 * DDIM) / 256, 256>>>(dw1, wh, wl);
    conv_mma_k<DDIM, HDIM, true><<<dim3(STILES, HDIM / 128), 256>>>(
        zq, wh, wl, db1, d1);

    wprep_k<HDIM, HDIM><<<(HDIM * 3 * HDIM) / 256, 256>>>(dw2, wh, wl);
    conv_mma_k<HDIM, HDIM, true><<<dim3(STILES, HDIM / 128), 256>>>(
        d1, wh, wl, db2, d2);

    dec3_k<<<(BATCH * SLEN) / 8, 256>>>(d2, dw3, db3, x, out);

    fin_k<<<1, 1>>>(out);
}